// round 8
// baseline (speedup 1.0000x reference)
#include <cuda_runtime.h>
#include <cuda_bf16.h>
#include <math.h>
#include <stdint.h>

#define BDIM   8
#define CC     256
#define NPIX   9216          // 96*96
#define RH     512           // R*HEADS
#define NHEADS 8
#define HDIM   32
#define RR     64

// ---------------- scratch (device globals; no allocations allowed) ----------
__device__ float g_Rq  [BDIM*RH*NPIX];
__device__ float g_Rk  [BDIM*RH*NPIX];
__device__ float g_tok [BDIM*CC*NPIX];
__device__ float g_m   [BDIM*NPIX];
__device__ float g_s   [BDIM*NPIX];
__device__ float g_rksum[BDIM*RH];
__device__ float g_S   [BDIM*CC*RH];          // [b][c][h*64+r]
__device__ float g_qr  [BDIM*NHEADS*HDIM*RR];
__device__ float g_vals[BDIM*NHEADS*HDIM*RR];

// bf16 hi/lo planes (16B aligned for uint4 loads)
__device__ __align__(16) __nv_bfloat16 g_Tt   [2ull*BDIM*NPIX*CC];  // tgt^T [2][b][n][k]
__device__ __align__(16) __nv_bfloat16 g_St   [2ull*BDIM*NPIX*CC];  // src^T
__device__ __align__(16) __nv_bfloat16 g_TOKt [2ull*BDIM*NPIX*CC];  // tok^T
__device__ __align__(16) __nv_bfloat16 g_Srcb [2ull*BDIM*CC*NPIX];  // src  [2][b][c][n]
__device__ __align__(16) __nv_bfloat16 g_Qb   [2ull*BDIM*CC*NPIX];  // q    [2][b][e][n]
__device__ __align__(16) __nv_bfloat16 g_Rqb  [2ull*BDIM*RH*NPIX];  // Rq sm [2][b][c][n]
__device__ __align__(16) __nv_bfloat16 g_Rkb  [2ull*BDIM*RH*NPIX];  // Rk sm
__device__ __align__(16) __nv_bfloat16 g_WqHL  [2*CC*CC];
__device__ __align__(16) __nv_bfloat16 g_WrqHL [2*RH*CC];
__device__ __align__(16) __nv_bfloat16 g_WrkHL [2*RH*CC];
__device__ __align__(16) __nv_bfloat16 g_WoutHL[2*CC*CC];

// ---------------- PTX helpers (baseline sm_80+ tensor path) ------------------
__device__ __forceinline__ uint32_t smem_u32(const void* p) {
    uint32_t a;
    asm("{ .reg .u64 t; cvta.to.shared.u64 t, %1; cvt.u32.u64 %0, t; }"
        : "=r"(a) : "l"(p));
    return a;
}
__device__ __forceinline__ void ldmx4(uint32_t* r, uint32_t addr) {
    asm volatile("ldmatrix.sync.aligned.m8n8.x4.shared.b16 {%0,%1,%2,%3}, [%4];"
        : "=r"(r[0]), "=r"(r[1]), "=r"(r[2]), "=r"(r[3]) : "r"(addr));
}
__device__ __forceinline__ void ldmx2(uint32_t* r, uint32_t addr) {
    asm volatile("ldmatrix.sync.aligned.m8n8.x2.shared.b16 {%0,%1}, [%2];"
        : "=r"(r[0]), "=r"(r[1]) : "r"(addr));
}
__device__ __forceinline__ void mma_bf16(float* c, const uint32_t* a, const uint32_t* b) {
    asm volatile("mma.sync.aligned.m16n8k16.row.col.f32.bf16.bf16.f32 "
        "{%0,%1,%2,%3}, {%4,%5,%6,%7}, {%8,%9}, {%0,%1,%2,%3};"
        : "+f"(c[0]), "+f"(c[1]), "+f"(c[2]), "+f"(c[3])
        : "r"(a[0]), "r"(a[1]), "r"(a[2]), "r"(a[3]), "r"(b[0]), "r"(b[1]));
}

// ---------------- misc small kernels ----------------------------------------
__global__ void zero_acc() {
    const int t1 = BDIM*CC*RH;
    const int t2 = BDIM*NHEADS*HDIM*RR;
    for (int i = blockIdx.x*blockDim.x + threadIdx.x; i < t1 + t2;
         i += gridDim.x*blockDim.x) {
        if (i < t1) g_S[i] = 0.f;
        else        g_qr[i - t1] = 0.f;
    }
}

// fp32 -> bf16 hi/lo planes (no transpose)
__global__ __launch_bounds__(256) void conv_w(
    const float* __restrict__ W, __nv_bfloat16* __restrict__ out, int total)
{
    int i = blockIdx.x*blockDim.x + threadIdx.x;
    if (i >= total) return;
    const float w = W[i];
    const __nv_bfloat16 hi = __float2bfloat16(w);
    out[i]         = hi;
    out[total + i] = __float2bfloat16(w - __bfloat162float(hi));
}

// X [B][256][9216] fp32 -> Xt [2][B][9216][256] bf16 (hi plane, lo plane)
__global__ __launch_bounds__(256) void transpose_conv(
    const float* __restrict__ X, __nv_bfloat16* __restrict__ Xt)
{
    __shared__ float tile[32][33];
    const int b = blockIdx.z, c0 = blockIdx.y*32, n0 = blockIdx.x*32;
    const int tx = threadIdx.x & 31, ty = threadIdx.x >> 5;   // 32x8
#pragma unroll
    for (int i = 0; i < 4; i++) {
        const int c = c0 + ty + 8*i;
        tile[ty + 8*i][tx] = X[((size_t)b*CC + c)*NPIX + n0 + tx];
    }
    __syncthreads();
    const size_t plane = (size_t)BDIM*NPIX*CC;
#pragma unroll
    for (int i = 0; i < 4; i++) {
        const int n = n0 + ty + 8*i;
        const float v = tile[tx][ty + 8*i];
        const __nv_bfloat16 hi = __float2bfloat16(v);
        const size_t o = ((size_t)b*NPIX + n)*CC + c0 + tx;
        Xt[o]         = hi;
        Xt[plane + o] = __float2bfloat16(v - __bfloat162float(hi));
    }
}

// ---------------- HMMA bf16x3 GEMM: Y = W @ X + bias -------------------------
// OM=0: fp32 out; OM=1: fp32 out with resid+alpha; OM=2: bf16 hi/lo planes out.
// CTA tile M=128 x N=128(pixels), K chunked by 64. 8 warps 2(M)x4(N).
template<int OM>
__global__ __launch_bounds__(256, 1) void hmma_gemm(
    const __nv_bfloat16* __restrict__ Whl, const float* __restrict__ bias,
    const __nv_bfloat16* __restrict__ Xt, float* __restrict__ Y,
    __nv_bfloat16* __restrict__ Ybf, int M,
    const float* __restrict__ resid, const float* __restrict__ alphap)
{
    extern __shared__ char sm[];
    const uint32_t sb = smem_u32(sm);
    const int tid = threadIdx.x, wid = tid >> 5, lane = tid & 31;
    const int n0 = blockIdx.x * 128, m0 = blockIdx.y * 128, b = blockIdx.z;
    const int mOff = (wid >> 2) * 64, nOff = (wid & 3) * 32;

    float acc[4][4][4];
#pragma unroll
    for (int mt = 0; mt < 4; mt++)
#pragma unroll
        for (int nt = 0; nt < 4; nt++)
#pragma unroll
            for (int i = 0; i < 4; i++) acc[mt][nt][i] = 0.f;

    const char* gA = (const char*)Whl + (size_t)m0 * 512;
    const size_t aPg = (size_t)M * 512;
    const char* gB = (const char*)Xt + ((size_t)b*NPIX + n0) * 512;
    const size_t bPg = (size_t)BDIM * NPIX * 512;

    const int tr = lane & 15, tc = lane >> 4;
    const int br = lane & 7,  bc = (lane >> 3) & 1;

    for (int k0 = 0; k0 < CC; k0 += 64) {
        __syncthreads();
#pragma unroll
        for (int p = 0; p < 2; p++) {
            const char* srcp = gA + p*aPg + k0*2;
            char* dst = sm + p*16384;
            for (int u = tid; u < 1024; u += 256) {
                const int row = u >> 3, c16 = u & 7;
                const uint4 v = *(const uint4*)(srcp + (size_t)row*512 + c16*16);
                *(uint4*)(dst + row*128 + ((c16 ^ (row & 7)) << 4)) = v;
            }
        }
#pragma unroll
        for (int p = 0; p < 2; p++) {
            const char* srcp = gB + p*bPg + k0*2;
            char* dst = sm + 32768 + p*16384;
            for (int u = tid; u < 1024; u += 256) {
                const int row = u >> 3, c16 = u & 7;
                const uint4 v = *(const uint4*)(srcp + (size_t)row*512 + c16*16);
                *(uint4*)(dst + row*128 + ((c16 ^ (row & 7)) << 4)) = v;
            }
        }
        __syncthreads();

#pragma unroll
        for (int kk = 0; kk < 4; kk++) {
            uint32_t ah[4][4], al_[4][4], bh[4][2], bl[4][2];
#pragma unroll
            for (int mt = 0; mt < 4; mt++) {
                const int row = mOff + mt*16 + tr;
                const int c16 = kk*2 + tc;
                const uint32_t ad = sb + row*128 + ((c16 ^ (row & 7)) << 4);
                ldmx4(ah[mt],  ad);
                ldmx4(al_[mt], ad + 16384);
            }
#pragma unroll
            for (int nt = 0; nt < 4; nt++) {
                const int row = nOff + nt*8 + br;
                const int c16 = kk*2 + bc;
                const uint32_t bd = sb + 32768 + row*128 + ((c16 ^ (row & 7)) << 4);
                ldmx2(bh[nt], bd);
                ldmx2(bl[nt], bd + 16384);
            }
#pragma unroll
            for (int mt = 0; mt < 4; mt++)
#pragma unroll
                for (int nt = 0; nt < 4; nt++) {
                    mma_bf16(acc[mt][nt], ah[mt],  bh[nt]);
                    mma_bf16(acc[mt][nt], ah[mt],  bl[nt]);
                    mma_bf16(acc[mt][nt], al_[mt], bh[nt]);
                }
        }
    }

    const float al = (OM == 1) ? *alphap : 0.f;
    const size_t PS = (size_t)BDIM * M * NPIX;
#pragma unroll
    for (int mt = 0; mt < 4; mt++) {
        const int r0 = m0 + mOff + mt*16 + (lane >> 2);
        const float bi0 = bias[r0], bi1 = bias[r0 + 8];
        const size_t base0 = ((size_t)b*M + r0)*NPIX + n0;
#pragma unroll
        for (int nt = 0; nt < 4; nt++) {
            const int c = nOff + nt*8 + 2*(lane & 3);
            float2 v0, v1;
            v0.x = acc[mt][nt][0] + bi0; v0.y = acc[mt][nt][1] + bi0;
            v1.x = acc[mt][nt][2] + bi1; v1.y = acc[mt][nt][3] + bi1;
            if (OM == 1) {
                const float2 a0 = *(const float2*)&resid[base0 + c];
                const float2 a1 = *(const float2*)&resid[base0 + 8*NPIX + c];
                v0.x = a0.x + al*v0.x; v0.y = a0.y + al*v0.y;
                v1.x = a1.x + al*v1.x; v1.y = a1.y + al*v1.y;
            }
            if (OM < 2) {
                *(float2*)&Y[base0 + c]          = v0;
                *(float2*)&Y[base0 + 8*NPIX + c] = v1;
            } else {
                __nv_bfloat162 h0, l0, h1, l1;
                h0.x = __float2bfloat16(v0.x);
                h0.y = __float2bfloat16(v0.y);
                l0.x = __float2bfloat16(v0.x - __bfloat162float(h0.x));
                l0.y = __float2bfloat16(v0.y - __bfloat162float(h0.y));
                h1.x = __float2bfloat16(v1.x);
                h1.y = __float2bfloat16(v1.y);
                l1.x = __float2bfloat16(v1.x - __bfloat162float(h1.x));
                l1.y = __float2bfloat16(v1.y - __bfloat162float(h1.y));
                *(__nv_bfloat162*)&Ybf[base0 + c]               = h0;
                *(__nv_bfloat162*)&Ybf[PS + base0 + c]          = l0;
                *(__nv_bfloat162*)&Ybf[base0 + 8*NPIX + c]      = h1;
                *(__nv_bfloat162*)&Ybf[PS + base0 + 8*NPIX + c] = l1;
            }
        }
    }
}

// ---- HMMA S: g_S[b][c][512] += src_b[256x9216] @ Rk_b^T[9216x512] (bf16x3) --
// grid: x = n-tile(4 of 128), y = m-tile(2 of 128), z = b*3 + ks (K split 3)
__global__ __launch_bounds__(256, 1) void hmma_S(
    const __nv_bfloat16* __restrict__ Ab, const __nv_bfloat16* __restrict__ Bb)
{
    extern __shared__ char sm[];
    const uint32_t sb = smem_u32(sm);
    const int tid = threadIdx.x, wid = tid >> 5, lane = tid & 31;
    const int nt0 = blockIdx.x * 128, m0 = blockIdx.y * 128;
    const int b = blockIdx.z / 3, ks = blockIdx.z % 3;
    const int mOff = (wid >> 2) * 64, nOff = (wid & 3) * 32;

    float acc[4][4][4];
#pragma unroll
    for (int mt = 0; mt < 4; mt++)
#pragma unroll
        for (int nt = 0; nt < 4; nt++)
#pragma unroll
            for (int i = 0; i < 4; i++) acc[mt][nt][i] = 0.f;

    const char* gA = (const char*)Ab + (((size_t)b*CC + m0)*NPIX + ks*3072) * 2;
    const size_t aPg = (size_t)BDIM * CC * NPIX * 2;
    const char* gB = (const char*)Bb + (((size_t)b*RH + nt0)*NPIX + ks*3072) * 2;
    const size_t bPg = (size_t)BDIM * RH * NPIX * 2;

    const int tr = lane & 15, tc = lane >> 4;
    const int br = lane & 7,  bc = (lane >> 3) & 1;

    for (int k0 = 0; k0 < 3072; k0 += 64) {
        __syncthreads();
#pragma unroll
        for (int p = 0; p < 2; p++) {
            const char* srcp = gA + p*aPg + k0*2;
            char* dst = sm + p*16384;
            for (int u = tid; u < 1024; u += 256) {
                const int row = u >> 3, c16 = u & 7;
                const uint4 v = *(const uint4*)(srcp + (size_t)row*18432 + c16*16);
                *(uint4*)(dst + row*128 + ((c16 ^ (row & 7)) << 4)) = v;
            }
        }
#pragma unroll
        for (int p = 0; p < 2; p++) {
            const char* srcp = gB + p*bPg + k0*2;
            char* dst = sm + 32768 + p*16384;
            for (int u = tid; u < 1024; u += 256) {
                const int row = u >> 3, c16 = u & 7;
                const uint4 v = *(const uint4*)(srcp + (size_t)row*18432 + c16*16);
                *(uint4*)(dst + row*128 + ((c16 ^ (row & 7)) << 4)) = v;
            }
        }
        __syncthreads();

#pragma unroll
        for (int kk = 0; kk < 4; kk++) {
            uint32_t ah[4][4], al_[4][4], bh[4][2], bl[4][2];
#pragma unroll
            for (int mt = 0; mt < 4; mt++) {
                const int row = mOff + mt*16 + tr;
                const int c16 = kk*2 + tc;
                const uint32_t ad = sb + row*128 + ((c16 ^ (row & 7)) << 4);
                ldmx4(ah[mt],  ad);
                ldmx4(al_[mt], ad + 16384);
            }
#pragma unroll
            for (int nt = 0; nt < 4; nt++) {
                const int row = nOff + nt*8 + br;
                const int c16 = kk*2 + bc;
                const uint32_t bd = sb + 32768 + row*128 + ((c16 ^ (row & 7)) << 4);
                ldmx2(bh[nt], bd);
                ldmx2(bl[nt], bd + 16384);
            }
#pragma unroll
            for (int mt = 0; mt < 4; mt++)
#pragma unroll
                for (int nt = 0; nt < 4; nt++) {
                    mma_bf16(acc[mt][nt], ah[mt],  bh[nt]);
                    mma_bf16(acc[mt][nt], ah[mt],  bl[nt]);
                    mma_bf16(acc[mt][nt], al_[mt], bh[nt]);
                }
        }
    }

#pragma unroll
    for (int mt = 0; mt < 4; mt++) {
        const int r0 = m0 + mOff + mt*16 + (lane >> 2);
        float* y0 = g_S + ((size_t)b*CC + r0)*RH + nt0;
        float* y1 = y0 + 8*RH;
#pragma unroll
        for (int nt = 0; nt < 4; nt++) {
            const int c = nOff + nt*8 + 2*(lane & 3);
            atomicAdd(&y0[c],   acc[mt][nt][0]);
            atomicAdd(&y0[c+1], acc[mt][nt][1]);
            atomicAdd(&y1[c],   acc[mt][nt][2]);
            atomicAdd(&y1[c+1], acc[mt][nt][3]);
        }
    }
}

// ---- HMMA qr: g_qr[b,h][32][64] += q_h[32x9216] @ Rq_h^T[9216x64] (bf16x3) --
// grid: x = bh (64), y = ks (4, K=2304 each). Static 24KB smem.
__global__ __launch_bounds__(256) void hmma_qr(
    const __nv_bfloat16* __restrict__ Qb, const __nv_bfloat16* __restrict__ Rqb)
{
    __shared__ char sm[24576];   // A: 2x4KB at 0, B: 2x8KB at 8192
    const uint32_t sb = smem_u32(sm);
    const int tid = threadIdx.x, wid = tid >> 5, lane = tid & 31;
    const int bh = blockIdx.x, ks = blockIdx.y;
    const int b = bh >> 3, h = bh & 7;
    const int mOff = (wid >> 2) * 16, nOff = (wid & 3) * 16;

    float acc[2][4];
#pragma unroll
    for (int nt = 0; nt < 2; nt++)
#pragma unroll
        for (int i = 0; i < 4; i++) acc[nt][i] = 0.f;

    const char* gA = (const char*)Qb + (((size_t)b*CC + h*HDIM)*NPIX + ks*2304) * 2;
    const size_t aPg = (size_t)BDIM * CC * NPIX * 2;
    const char* gB = (const char*)Rqb + (((size_t)b*RH + h*RR)*NPIX + ks*2304) * 2;
    const size_t bPg = (size_t)BDIM * RH * NPIX * 2;

    const int tr = lane & 15, tc = lane >> 4;
    const int br = lane & 7,  bc = (lane >> 3) & 1;

    for (int k0 = 0; k0 < 2304; k0 += 64) {
        __syncthreads();
#pragma unroll
        for (int p = 0; p < 2; p++) {        // A: 32 rows x 128B
            const char* srcp = gA + p*aPg + k0*2;
            char* dst = sm + p*4096;
            if (tid < 256) {
                const int u = tid;           // 256 loads exactly
                const int row = u >> 3, c16 = u & 7;
                const uint4 v = *(const uint4*)(srcp + (size_t)row*18432 + c16*16);
                *(uint4*)(dst + row*128 + ((c16 ^ (row & 7)) << 4)) = v;
            }
        }
#pragma unroll
        for (int p = 0; p < 2; p++) {        // B: 64 rows x 128B
            const char* srcp = gB + p*bPg + k0*2;
            char* dst = sm + 8192 + p*8192;
            for (int u = tid; u < 512; u += 256) {
                const int row = u >> 3, c16 = u & 7;
                const uint4 v = *(const uint4*)(srcp + (size_t)row*18432 + c16*16);
                *(uint4*)(dst + row*128 + ((c16 ^ (row & 7)) << 4)) = v;
            }
        }
        __syncthreads();

#pragma unroll
        for (int kk = 0; kk < 4; kk++) {
            uint32_t ah[4], al_[4], bh2[2][2], bl2[2][2];
            {
                const int row = mOff + tr;
                const int c16 = kk*2 + tc;
                const uint32_t ad = sb + row*128 + ((c16 ^ (row & 7)) << 4);
                ldmx4(ah,  ad);
                ldmx4(al_, ad + 4096);
            }
#pragma unroll
            for (int nt = 0; nt < 2; nt++) {
                const int row = nOff + nt*8 + br;
                const int c16 = kk*2 + bc;
                const uint32_t bd = sb + 8192 + row*128 + ((c16 ^ (row & 7)) << 4);
                ldmx2(bh2[nt], bd);
                ldmx2(bl2[nt], bd + 8192);
            }
#pragma unroll
            for (int nt = 0; nt < 2; nt++) {
                mma_bf16(acc[nt], ah,  bh2[nt]);
                mma_bf16(acc[nt], ah,  bl2[nt]);
                mma_bf16(acc[nt], al_, bh2[nt]);
            }
        }
    }

    const int r0 = mOff + (lane >> 2);
    float* y0 = g_qr + (size_t)bh*HDIM*RR + (size_t)r0*RR;
    float* y1 = y0 + 8*RR;
#pragma unroll
    for (int nt = 0; nt < 2; nt++) {
        const int c = nOff + nt*8 + 2*(lane & 3);
        atomicAdd(&y0[c],   acc[nt][0]);
        atomicAdd(&y0[c+1], acc[nt][1]);
        atomicAdd(&y1[c],   acc[nt][2]);
        atomicAdd(&y1[c+1], acc[nt][3]);
    }
}

// ---- channel softmax over 512 channels, per pixel column -------------------
__global__ __launch_bounds__(256) void softmax_ch_pass1(
    const float* __restrict__ X, float* __restrict__ gm, float* __restrict__ gs)
{
    const int idx = blockIdx.x * blockDim.x + threadIdx.x;
    if (idx >= BDIM*NPIX) return;
    const int b = idx / NPIX, n = idx - b*NPIX;
    const float* col = X + (size_t)b*RH*NPIX + n;
    float m = -1e30f, s = 0.f;
    for (int c = 0; c < RH; c++) {
        const float x = col[(size_t)c*NPIX];
        const float m2 = fmaxf(m, x);
        s = s * __expf(m - m2) + __expf(x - m2);
        m = m2;
    }
    gm[idx] = m; gs[idx] = s;
}

// pass2: normalize, emit bf16 hi/lo planes; optional fp32 writeback
template<bool WF32>
__global__ __launch_bounds__(256) void softmax_ch_pass2b(
    float* __restrict__ X, const float* __restrict__ gm,
    const float* __restrict__ gs, __nv_bfloat16* __restrict__ Xb)
{
    const int idx = blockIdx.x * blockDim.x + threadIdx.x;
    if (idx >= BDIM*NPIX) return;
    const int b = idx / NPIX, n = idx - b*NPIX;
    float* col = X + (size_t)b*RH*NPIX + n;
    __nv_bfloat16* colb = Xb + (size_t)b*RH*NPIX + n;
    const size_t PS = (size_t)BDIM*RH*NPIX;
    const float m = gm[idx], inv = 1.f / gs[idx];
    for (int c = 0; c < RH; c++) {
        const float v = __expf(col[(size_t)c*NPIX] - m) * inv;
        if (WF32) col[(size_t)c*NPIX] = v;
        const __nv_bfloat16 hi = __float2bfloat16(v);
        colb[(size_t)c*NPIX]      = hi;
        colb[PS + (size_t)c*NPIX] = __float2bfloat16(v - __bfloat162float(hi));
    }
}

// ---- row sums of softmaxed Rk (from bf16 hi+lo planes) ---------------------
__global__ __launch_bounds__(256) void rowsum_rk(const __nv_bfloat16* __restrict__ Rkb) {
    const int row = blockIdx.x;                 // B*RH rows
    const size_t PS = (size_t)BDIM*RH*NPIX;
    const __nv_bfloat16* ph = Rkb + (size_t)row * NPIX;
    float s = 0.f;
    for (int n = threadIdx.x; n < NPIX; n += 256)
        s += __bfloat162float(ph[n]) + __bfloat162float(ph[PS + n]);
    __shared__ float red[256];
    red[threadIdx.x] = s; __syncthreads();
    for (int o = 128; o > 0; o >>= 1) {
        if (threadIdx.x < o) red[threadIdx.x] += red[threadIdx.x + o];
        __syncthreads();
    }
    if (threadIdx.x == 0) g_rksum[row] = red[0];
}

// ---- per-(b,h): kv fold, 64x64 attention, vals -----------------------------
__global__ __launch_bounds__(256) void attn_small(
    const float* __restrict__ Wkv, const float* __restrict__ bkv)
{
    const int bh = blockIdx.x;
    const int b = bh >> 3, h = bh & 7;
    __shared__ float segA[RR*65];
    __shared__ float segB[RR*65];
    __shared__ float segC[HDIM*65];
    const int tid = threadIdx.x;

    const int r1 = tid & 63, jg = tid >> 6;
    float acc[16];
#pragma unroll
    for (int jj = 0; jj < 16; jj++) acc[jj] = 0.f;
    const float* Sp = g_S + (size_t)b*CC*RH + h*RR;   // [c]*RH + r
    const float* Wp = Wkv + (size_t)(h*64)*CC;
    for (int c0 = 0; c0 < CC; c0 += 64) {
        for (int v = tid; v < 64*64; v += 256) {
            int cc = v >> 6, rr2 = v & 63;
            segA[cc*65 + rr2] = Sp[(size_t)(c0+cc)*RH + rr2];
        }
        for (int v = tid; v < 64*64; v += 256) {
            int j = v >> 6, cc = v & 63;
            segB[j*65 + cc] = Wp[(size_t)j*CC + c0 + cc];
        }
        __syncthreads();
        for (int cc = 0; cc < 64; cc++) {
            const float sv = segA[cc*65 + r1];
#pragma unroll
            for (int jj = 0; jj < 16; jj++)
                acc[jj] += segB[(jg*16+jj)*65 + cc] * sv;
        }
        __syncthreads();
    }
    {
        const float rs = g_rksum[b*RH + h*RR + r1];
#pragma unroll
        for (int jj = 0; jj < 16; jj++) {
            const int j = jg*16 + jj;
            segA[j*65 + r1] = acc[jj] + bkv[h*64 + j] * rs;
        }
    }
    for (int v = tid; v < HDIM*RR; v += 256) {
        int d = v >> 6, q = v & 63;
        segC[d*65 + q] = g_qr[(size_t)bh*HDIM*RR + v];
    }
    __syncthreads();

    {
        const float scale = rsqrtf((float)HDIM);
        const int k2 = tid & 63, qg = tid >> 6;
        for (int qq = 0; qq < 16; qq++) {
            const int q = qg*16 + qq;
            float s = 0.f;
#pragma unroll 8
            for (int d = 0; d < HDIM; d++)
                s += segC[d*65 + q] * segA[d*65 + k2];
            segB[q*65 + k2] = s * scale;
        }
    }
    __syncthreads();

    if (tid < 64) {
        float m = -1e30f;
        for (int k = 0; k < 64; k++) m = fmaxf(m, segB[tid*65 + k]);
        float s = 0.f;
        for (int k = 0; k < 64; k++) {
            const float e = __expf(segB[tid*65 + k] - m);
            segB[tid*65 + k] = e; s += e;
        }
        const float inv = 1.f / s;
        for (int k = 0; k < 64; k++) segB[tid*65 + k] *= inv;
    }
    __syncthreads();

    {
        const int q = tid & 63, dg = tid >> 6;
        float vacc[8];
#pragma unroll
        for (int dd = 0; dd < 8; dd++) vacc[dd] = 0.f;
        for (int k = 0; k < 64; k++) {
            const float av = segB[q*65 + k];
#pragma unroll
            for (int dd = 0; dd < 8; dd++)
                vacc[dd] += segA[(HDIM + dg*8 + dd)*65 + k] * av;
        }
#pragma unroll
        for (int dd = 0; dd < 8; dd++)
            g_vals[(size_t)bh*HDIM*RR + (dg*8+dd)*RR + q] = vacc[dd];
    }
}

// ---- tok[b][h*32+d][n] = sum_r vals[d][r]*Rq[h*64+r][n] --------------------
__global__ __launch_bounds__(256) void tok_kernel() {
    const int bh = blockIdx.y;
    const int b = bh >> 3, h = bh & 7;
    const int n0 = blockIdx.x * 256;
    __shared__ float Vt[RR][33];
    __shared__ float Bs[16][257];
    const int tid = threadIdx.x;
    for (int v = tid; v < HDIM*RR; v += 256) {
        int d = v >> 6, rr2 = v & 63;
        Vt[rr2][d] = g_vals[(size_t)bh*HDIM*RR + v];
    }
    const int lane = tid & 31, d0 = (tid >> 5) * 4;
    float acc[4][8];
#pragma unroll
    for (int i = 0; i < 4; i++)
#pragma unroll
        for (int j = 0; j < 8; j++) acc[i][j] = 0.f;
    const float* Rp = g_Rq + ((size_t)b*RH + h*RR)*NPIX + n0;
    for (int r0 = 0; r0 < RR; r0 += 16) {
        for (int v = tid; v < 16*256; v += 256) {
            int rr2 = v >> 8, nn = v & 255;
            Bs[rr2][nn] = Rp[(size_t)(r0+rr2)*NPIX + nn];
        }
        __syncthreads();
#pragma unroll 4
        for (int rr2 = 0; rr2 < 16; rr2++) {
            float a[4];
#pragma unroll
            for (int i = 0; i < 4; i++) a[i] = Vt[r0+rr2][d0+i];
#pragma unroll
            for (int j = 0; j < 8; j++) {
                const float bv = Bs[rr2][lane + j*32];
#pragma unroll
                for (int i = 0; i < 4; i++) acc[i][j] += a[i] * bv;
            }
        }
        __syncthreads();
    }
#pragma unroll
    for (int i = 0; i < 4; i++) {
        float* trow = g_tok + ((size_t)b*CC + h*HDIM + d0+i)*NPIX + n0;
#pragma unroll
        for (int j = 0; j < 8; j++) trow[lane + j*32] = acc[i][j];
    }
}

// ---- host launcher ----------------------------------------------------------
extern "C" void kernel_launch(void* const* d_in, const int* in_sizes, int n_in,
                              void* d_out, int out_size)
{
    const float* src    = (const float*)d_in[0];
    const float* tgt    = (const float*)d_in[1];
    const float* Wq     = (const float*)d_in[2];
    const float* bq     = (const float*)d_in[3];
    const float* Wkv    = (const float*)d_in[4];
    const float* bkv    = (const float*)d_in[5];
    const float* Wrq    = (const float*)d_in[6];
    const float* brq    = (const float*)d_in[7];
    const float* Wrk    = (const float*)d_in[8];
    const float* brk    = (const float*)d_in[9];
    const float* Wout   = (const float*)d_in[10];
    const float* bout   = (const float*)d_in[11];
    const float* alphap = (const float*)d_in[12];
    float* out = (float*)d_out;

    float *pRq, *pRk, *ptok, *pm, *ps;
    __nv_bfloat16 *pTt, *pSt, *pTOKt, *pSrcb, *pQb, *pRqb, *pRkb;
    __nv_bfloat16 *pWq, *pWrq, *pWrk, *pWout;
    cudaGetSymbolAddress((void**)&pRq,   g_Rq);
    cudaGetSymbolAddress((void**)&pRk,   g_Rk);
    cudaGetSymbolAddress((void**)&ptok,  g_tok);
    cudaGetSymbolAddress((void**)&pm,    g_m);
    cudaGetSymbolAddress((void**)&ps,    g_s);
    cudaGetSymbolAddress((void**)&pTt,   g_Tt);
    cudaGetSymbolAddress((void**)&pSt,   g_St);
    cudaGetSymbolAddress((void**)&pTOKt, g_TOKt);
    cudaGetSymbolAddress((void**)&pSrcb, g_Srcb);
    cudaGetSymbolAddress((void**)&pQb,   g_Qb);
    cudaGetSymbolAddress((void**)&pRqb,  g_Rqb);
    cudaGetSymbolAddress((void**)&pRkb,  g_Rkb);
    cudaGetSymbolAddress((void**)&pWq,   g_WqHL);
    cudaGetSymbolAddress((void**)&pWrq,  g_WrqHL);
    cudaGetSymbolAddress((void**)&pWrk,  g_WrkHL);
    cudaGetSymbolAddress((void**)&pWout, g_WoutHL);

    const int SMEM = 65536;
    cudaFuncSetAttribute(hmma_gemm<0>,
        cudaFuncAttributeMaxDynamicSharedMemorySize, SMEM);
    cudaFuncSetAttribute(hmma_gemm<1>,
        cudaFuncAttributeMaxDynamicSharedMemorySize, SMEM);
    cudaFuncSetAttribute(hmma_gemm<2>,
        cudaFuncAttributeMaxDynamicSharedMemorySize, SMEM);
    cudaFuncSetAttribute(hmma_S,
        cudaFuncAttributeMaxDynamicSharedMemorySize, SMEM);

    zero_acc<<<512, 256>>>();

    conv_w<<<(CC*CC + 255)/256, 256>>>(Wq,   pWq,   CC*CC);
    conv_w<<<(RH*CC + 255)/256, 256>>>(Wrq,  pWrq,  RH*CC);
    conv_w<<<(RH*CC + 255)/256, 256>>>(Wrk,  pWrk,  RH*CC);
    conv_w<<<(CC*CC + 255)/256, 256>>>(Wout, pWout, CC*CC);
    conv_w<<<(BDIM*CC*NPIX + 255)/256, 256>>>(src, pSrcb, BDIM*CC*NPIX);

    dim3 gt(NPIX/32, CC/32, BDIM);     // 288, 8, 8
    transpose_conv<<<gt, 256>>>(tgt, pTt);
    transpose_conv<<<gt, 256>>>(src, pSt);

    dim3 g2(NPIX/128, CC/128, BDIM);   // 72, 2, 8
    dim3 g4(NPIX/128, RH/128, BDIM);   // 72, 4, 8
    hmma_gemm<2><<<g2, 256, SMEM>>>(pWq,  bq,  pTt, nullptr, pQb, CC, nullptr, nullptr);
    hmma_gemm<0><<<g4, 256, SMEM>>>(pWrq, brq, pTt, pRq, nullptr, RH, nullptr, nullptr);
    hmma_gemm<0><<<g4, 256, SMEM>>>(pWrk, brk, pSt, pRk, nullptr, RH, nullptr, nullptr);

    const int sgrid = (BDIM*NPIX + 255) / 256;   // 288
    softmax_ch_pass1<<<sgrid, 256>>>(pRq, pm, ps);
    softmax_ch_pass2b<true ><<<sgrid, 256>>>(pRq, pm, ps, pRqb);
    softmax_ch_pass1<<<sgrid, 256>>>(pRk, pm, ps);
    softmax_ch_pass2b<false><<<sgrid, 256>>>(pRk, pm, ps, pRkb);

    rowsum_rk<<<BDIM*RH, 256>>>(pRkb);

    hmma_qr<<<dim3(BDIM*NHEADS, 4), 256>>>(pQb, pRqb);
    hmma_S <<<dim3(4, 2, BDIM*3), 256, SMEM>>>(pSrcb, pRkb);

    attn_small<<<BDIM*NHEADS, 256>>>(Wkv, bkv);

    tok_kernel<<<dim3(NPIX/256, BDIM*NHEADS), 256>>>();

    transpose_conv<<<gt, 256>>>(ptok, pTOKt);
    hmma_gemm<1><<<g2, 256, SMEM>>>(pWout, bout, pTOKt, out, nullptr, CC, tgt, alphap);
}

// round 10
// speedup vs baseline: 1.9064x; 1.9064x over previous
#include <cuda_runtime.h>
#include <cuda_bf16.h>
#include <math.h>
#include <stdint.h>

#define BDIM   8
#define CC     256
#define NPIX   9216          // 96*96
#define RH     512           // R*HEADS
#define NHEADS 8
#define HDIM   32
#define RR     64

// ---------------- scratch (device globals; no allocations allowed) ----------
__device__ float g_q   [BDIM*CC*NPIX];
__device__ float g_Rq  [BDIM*RH*NPIX];
__device__ float g_Rk  [BDIM*RH*NPIX];
__device__ float g_tok [BDIM*CC*NPIX];
__device__ float g_m   [BDIM*NPIX];
__device__ float g_s   [BDIM*NPIX];
__device__ float g_rksum[BDIM*RH];
__device__ float g_S   [BDIM*NHEADS*CC*RR];
__device__ float g_qr  [BDIM*NHEADS*HDIM*RR];
__device__ float g_vals[BDIM*NHEADS*HDIM*RR];

// bf16 hi/lo planes (16B aligned for uint4 loads)
__device__ __align__(16) __nv_bfloat16 g_Tt  [2ull*BDIM*NPIX*CC];  // tgt^T [2][b][n][k]
__device__ __align__(16) __nv_bfloat16 g_St  [2ull*BDIM*NPIX*CC];  // src^T
__device__ __align__(16) __nv_bfloat16 g_TOKt[2ull*BDIM*NPIX*CC];  // tok^T
__device__ __align__(16) __nv_bfloat16 g_WqHL  [2*CC*CC];
__device__ __align__(16) __nv_bfloat16 g_WrqHL [2*RH*CC];
__device__ __align__(16) __nv_bfloat16 g_WrkHL [2*RH*CC];
__device__ __align__(16) __nv_bfloat16 g_WoutHL[2*CC*CC];

// ---------------- PTX helpers (baseline sm_80+ tensor path) ------------------
__device__ __forceinline__ uint32_t smem_u32(const void* p) {
    uint32_t a;
    asm("{ .reg .u64 t; cvta.to.shared.u64 t, %1; cvt.u32.u64 %0, t; }"
        : "=r"(a) : "l"(p));
    return a;
}
__device__ __forceinline__ void ldmx4(uint32_t* r, uint32_t addr) {
    asm volatile("ldmatrix.sync.aligned.m8n8.x4.shared.b16 {%0,%1,%2,%3}, [%4];"
        : "=r"(r[0]), "=r"(r[1]), "=r"(r[2]), "=r"(r[3]) : "r"(addr));
}
__device__ __forceinline__ void ldmx2(uint32_t* r, uint32_t addr) {
    asm volatile("ldmatrix.sync.aligned.m8n8.x2.shared.b16 {%0,%1}, [%2];"
        : "=r"(r[0]), "=r"(r[1]) : "r"(addr));
}
__device__ __forceinline__ void mma_bf16(float* c, const uint32_t* a, const uint32_t* b) {
    asm volatile("mma.sync.aligned.m16n8k16.row.col.f32.bf16.bf16.f32 "
        "{%0,%1,%2,%3}, {%4,%5,%6,%7}, {%8,%9}, {%0,%1,%2,%3};"
        : "+f"(c[0]), "+f"(c[1]), "+f"(c[2]), "+f"(c[3])
        : "r"(a[0]), "r"(a[1]), "r"(a[2]), "r"(a[3]), "r"(b[0]), "r"(b[1]));
}
__device__ __forceinline__ void cp16(uint32_t dst, const void* src) {
    asm volatile("cp.async.cg.shared.global [%0], [%1], 16;"
                 :: "r"(dst), "l"(src));
}
#define CP_COMMIT() asm volatile("cp.async.commit_group;" ::: "memory")
#define CP_WAIT(n)  asm volatile("cp.async.wait_group %0;" :: "n"(n) : "memory")

// ---------------- misc small kernels ----------------------------------------
__global__ void zero_acc() {
    const int t1 = BDIM*NHEADS*CC*RR;
    const int t2 = BDIM*NHEADS*HDIM*RR;
    for (int i = blockIdx.x*blockDim.x + threadIdx.x; i < t1 + t2;
         i += gridDim.x*blockDim.x) {
        if (i < t1) g_S[i] = 0.f;
        else        g_qr[i - t1] = 0.f;
    }
}

__global__ __launch_bounds__(256) void conv_w(
    const float* __restrict__ W, __nv_bfloat16* __restrict__ out, int total)
{
    int i = blockIdx.x*blockDim.x + threadIdx.x;
    if (i >= total) return;
    const float w = W[i];
    const __nv_bfloat16 hi = __float2bfloat16(w);
    out[i]         = hi;
    out[total + i] = __float2bfloat16(w - __bfloat162float(hi));
}

// X [B][256][9216] fp32 -> Xt [2][B][9216][256] bf16 (hi plane, lo plane)
__global__ __launch_bounds__(256) void transpose_conv(
    const float* __restrict__ X, __nv_bfloat16* __restrict__ Xt)
{
    __shared__ float tile[32][33];
    const int b = blockIdx.z, c0 = blockIdx.y*32, n0 = blockIdx.x*32;
    const int tx = threadIdx.x & 31, ty = threadIdx.x >> 5;   // 32x8
#pragma unroll
    for (int i = 0; i < 4; i++) {
        const int c = c0 + ty + 8*i;
        tile[ty + 8*i][tx] = X[((size_t)b*CC + c)*NPIX + n0 + tx];
    }
    __syncthreads();
    const size_t plane = (size_t)BDIM*NPIX*CC;
#pragma unroll
    for (int i = 0; i < 4; i++) {
        const int n = n0 + ty + 8*i;
        const float v = tile[tx][ty + 8*i];
        const __nv_bfloat16 hi = __float2bfloat16(v);
        const size_t o = ((size_t)b*NPIX + n)*CC + c0 + tx;
        Xt[o]         = hi;
        Xt[plane + o] = __float2bfloat16(v - __bfloat162float(hi));
    }
}

// ---------------- HMMA bf16x3 GEMM, 2-stage cp.async pipeline ----------------
// CTA tile M=128 x N=128(pixels), K chunked by 64. 8 warps 2(M)x4(N).
// Stage layout (64KB): A hi 16K | A lo 16K | B hi 16K | B lo 16K. 2 stages.
template<bool RESID>
__global__ __launch_bounds__(256, 1) void hmma_gemm(
    const __nv_bfloat16* __restrict__ Whl, const float* __restrict__ bias,
    const __nv_bfloat16* __restrict__ Xt, float* __restrict__ Y, int M,
    const float* __restrict__ resid, const float* __restrict__ alphap)
{
    extern __shared__ char sm[];
    const uint32_t sb = smem_u32(sm);
    const int tid = threadIdx.x, wid = tid >> 5, lane = tid & 31;
    const int n0 = blockIdx.x * 128, m0 = blockIdx.y * 128, b = blockIdx.z;
    const int mOff = (wid >> 2) * 64, nOff = (wid & 3) * 32;

    float acc[4][4][4];
#pragma unroll
    for (int mt = 0; mt < 4; mt++)
#pragma unroll
        for (int nt = 0; nt < 4; nt++)
#pragma unroll
            for (int i = 0; i < 4; i++) acc[mt][nt][i] = 0.f;

    const char* gA = (const char*)Whl + (size_t)m0 * 512;
    const size_t aPg = (size_t)M * 512;
    const char* gB = (const char*)Xt + ((size_t)b*NPIX + n0) * 512;
    const size_t bPg = (size_t)BDIM * NPIX * 512;

    const int lr = tid >> 3, lc = tid & 7;   // fill: 32 rows x 8 c16 per pass

    // issue one 64-K chunk into stage stg
#define ISSUE(k0, stg) do {                                                    \
    const uint32_t base_ = sb + (stg)*65536;                                   \
    _Pragma("unroll")                                                          \
    for (int p = 0; p < 2; p++) {                                              \
        const char* sA = gA + p*aPg + (k0)*2;                                  \
        const char* sB = gB + p*bPg + (k0)*2;                                  \
        _Pragma("unroll")                                                      \
        for (int it = 0; it < 4; it++) {                                       \
            const int row = lr + it*32;                                        \
            const uint32_t sw = row*128 + ((lc ^ (row & 7)) << 4);             \
            cp16(base_ + p*16384 + sw,         sA + (size_t)row*512 + lc*16);  \
            cp16(base_ + 32768 + p*16384 + sw, sB + (size_t)row*512 + lc*16);  \
        }                                                                      \
    }                                                                          \
    CP_COMMIT();                                                               \
} while (0)

    const int tr = lane & 15, tc = lane >> 4;
    const int br = lane & 7,  bc = (lane >> 3) & 1;

    ISSUE(0, 0);
#pragma unroll
    for (int c = 0; c < 4; c++) {
        if (c < 3) { ISSUE((c+1)*64, (c+1) & 1); CP_WAIT(1); }
        else       { CP_WAIT(0); }
        __syncthreads();
        const uint32_t base = sb + (c & 1)*65536;

#pragma unroll
        for (int kk = 0; kk < 4; kk++) {
            uint32_t ah[4][4], al_[4][4], bh[4][2], bl[4][2];
#pragma unroll
            for (int mt = 0; mt < 4; mt++) {
                const int row = mOff + mt*16 + tr;
                const int c16 = kk*2 + tc;
                const uint32_t ad = base + row*128 + ((c16 ^ (row & 7)) << 4);
                ldmx4(ah[mt],  ad);
                ldmx4(al_[mt], ad + 16384);
            }
#pragma unroll
            for (int nt = 0; nt < 4; nt++) {
                const int row = nOff + nt*8 + br;
                const int c16 = kk*2 + bc;
                const uint32_t bd = base + 32768 + row*128 + ((c16 ^ (row & 7)) << 4);
                ldmx2(bh[nt], bd);
                ldmx2(bl[nt], bd + 16384);
            }
#pragma unroll
            for (int mt = 0; mt < 4; mt++)
#pragma unroll
                for (int nt = 0; nt < 4; nt++) {
                    mma_bf16(acc[mt][nt], ah[mt],  bh[nt]);
                    mma_bf16(acc[mt][nt], ah[mt],  bl[nt]);
                    mma_bf16(acc[mt][nt], al_[mt], bh[nt]);
                }
        }
        __syncthreads();
    }
#undef ISSUE

    const float al = RESID ? *alphap : 0.f;
#pragma unroll
    for (int mt = 0; mt < 4; mt++) {
        const int r0 = m0 + mOff + mt*16 + (lane >> 2);
        const float bi0 = bias[r0], bi1 = bias[r0 + 8];
        float* y0 = Y + ((size_t)b*M + r0)*NPIX + n0;
        float* y1 = y0 + 8*NPIX;
        const float* rr0 = RESID ? (resid + ((size_t)b*M + r0)*NPIX + n0) : nullptr;
        const float* rr1 = RESID ? rr0 + 8*NPIX : nullptr;
#pragma unroll
        for (int nt = 0; nt < 4; nt++) {
            const int c = nOff + nt*8 + 2*(lane & 3);
            float2 v0, v1;
            v0.x = acc[mt][nt][0] + bi0; v0.y = acc[mt][nt][1] + bi0;
            v1.x = acc[mt][nt][2] + bi1; v1.y = acc[mt][nt][3] + bi1;
            if (RESID) {
                const float2 a0 = *(const float2*)&rr0[c];
                const float2 a1 = *(const float2*)&rr1[c];
                v0.x = a0.x + al*v0.x; v0.y = a0.y + al*v0.y;
                v1.x = a1.x + al*v1.x; v1.y = a1.y + al*v1.y;
            }
            *(float2*)&y0[c] = v0;
            *(float2*)&y1[c] = v1;
        }
    }
}

// ---- channel softmax over 512 channels, per pixel column -------------------
__global__ __launch_bounds__(256) void softmax_ch_pass1(
    const float* __restrict__ X, float* __restrict__ gm, float* __restrict__ gs)
{
    const int idx = blockIdx.x * blockDim.x + threadIdx.x;
    if (idx >= BDIM*NPIX) return;
    const int b = idx / NPIX, n = idx - b*NPIX;
    const float* col = X + (size_t)b*RH*NPIX + n;
    float m = -1e30f, s = 0.f;
    for (int c = 0; c < RH; c++) {
        const float x = col[(size_t)c*NPIX];
        const float m2 = fmaxf(m, x);
        s = s * __expf(m - m2) + __expf(x - m2);
        m = m2;
    }
    gm[idx] = m; gs[idx] = s;
}

__global__ __launch_bounds__(256) void softmax_ch_pass2(
    float* __restrict__ X, const float* __restrict__ gm, const float* __restrict__ gs)
{
    const int idx = blockIdx.x * blockDim.x + threadIdx.x;
    if (idx >= BDIM*NPIX) return;
    const int b = idx / NPIX, n = idx - b*NPIX;
    float* col = X + (size_t)b*RH*NPIX + n;
    const float m = gm[idx], inv = 1.f / gs[idx];
    for (int c = 0; c < RH; c++) {
        float* p = col + (size_t)c*NPIX;
        *p = __expf(*p - m) * inv;
    }
}

// ---- row sums of softmaxed Rk ----------------------------------------------
__global__ __launch_bounds__(256) void rowsum_rk() {
    const int row = blockIdx.x;                 // B*RH rows
    const float* p = g_Rk + (size_t)row * NPIX;
    float s = 0.f;
    for (int n = threadIdx.x; n < NPIX; n += 256) s += p[n];
    __shared__ float red[256];
    red[threadIdx.x] = s; __syncthreads();
    for (int o = 128; o > 0; o >>= 1) {
        if (threadIdx.x < o) red[threadIdx.x] += red[threadIdx.x + o];
        __syncthreads();
    }
    if (threadIdx.x == 0) g_rksum[row] = red[0];
}

// ---- qr[b,h][32x64] = q_h @ Rq_h^T  (K-split over NPIX, atomic) ------------
__global__ __launch_bounds__(256) void contract_qr() {
    const int bh = blockIdx.x;
    const int b = bh >> 3, h = bh & 7;
    const int kbase = blockIdx.y * 512;
    const float* Q  = g_q  + ((size_t)b*CC + h*HDIM)*NPIX;
    const float* Rr = g_Rq + ((size_t)b*RH + h*RR)*NPIX;
    __shared__ float Qs[HDIM][33];
    __shared__ float Rs[RR][33];
    const int tid = threadIdx.x;
    const int r = tid & 63, d0 = (tid >> 6) * 8;
    float acc[8] = {};
    for (int t = 0; t < 16; t++) {
        const int kg = kbase + t*32;
        for (int v = tid; v < HDIM*32; v += 256) {
            int i = v >> 5, kk = v & 31;
            Qs[i][kk] = Q[(size_t)i*NPIX + kg + kk];
        }
        for (int v = tid; v < RR*32; v += 256) {
            int i = v >> 5, kk = v & 31;
            Rs[i][kk] = Rr[(size_t)i*NPIX + kg + kk];
        }
        __syncthreads();
#pragma unroll 4
        for (int kk = 0; kk < 32; kk++) {
            const float rv = Rs[r][kk];
#pragma unroll
            for (int i = 0; i < 8; i++) acc[i] += Qs[d0+i][kk] * rv;
        }
        __syncthreads();
    }
#pragma unroll
    for (int i = 0; i < 8; i++)
        atomicAdd(&g_qr[(size_t)bh*HDIM*RR + (d0+i)*RR + r], acc[i]);
}

// ---- S[b,h][256x64] = src_b @ Rk_h^T  (K-split, atomic) --------------------
// Transposed smem tiles -> float4 LDS, high FMA density.
__global__ __launch_bounds__(256) void contract_S(const float* __restrict__ src) {
    const int bh = blockIdx.x;
    const int b = bh >> 3, h = bh & 7;
    const int m0 = blockIdx.y * 128;
    const int kbase = blockIdx.z * 2304;
    const float* Sx = src  + ((size_t)b*CC + m0)*NPIX;
    const float* Rr = g_Rk + ((size_t)b*RH + h*RR)*NPIX;
    __shared__ float AsmT[32][132];   // [kk][m], row = 528B (16B mult)
    __shared__ float RsT[32][68];     // [kk][r], row = 272B (16B mult)
    const int tid = threadIdx.x;
    const int mq = (tid >> 4) * 8, rq = (tid & 15) * 4;
    float acc[8][4];
#pragma unroll
    for (int i = 0; i < 8; i++)
#pragma unroll
        for (int j = 0; j < 4; j++) acc[i][j] = 0.f;
    for (int t = 0; t < 72; t++) {
        const int kg = kbase + t*32;
        for (int v = tid; v < 128*32; v += 256) {
            int i = v >> 5, kk = v & 31;
            AsmT[kk][i] = Sx[(size_t)i*NPIX + kg + kk];
        }
        for (int v = tid; v < 64*32; v += 256) {
            int i = v >> 5, kk = v & 31;
            RsT[kk][i] = Rr[(size_t)i*NPIX + kg + kk];
        }
        __syncthreads();
#pragma unroll 8
        for (int kk = 0; kk < 32; kk++) {
            float a[8], bb[4];
            *(float4*)&a[0]  = *(const float4*)&AsmT[kk][mq];
            *(float4*)&a[4]  = *(const float4*)&AsmT[kk][mq+4];
            *(float4*)&bb[0] = *(const float4*)&RsT[kk][rq];
#pragma unroll
            for (int i = 0; i < 8; i++)
#pragma unroll
                for (int j = 0; j < 4; j++) acc[i][j] += a[i] * bb[j];
        }
        __syncthreads();
    }
#pragma unroll
    for (int i = 0; i < 8; i++)
#pragma unroll
        for (int j = 0; j < 4; j++)
            atomicAdd(&g_S[((size_t)bh*CC + m0+mq+i)*RR + rq+j], acc[i][j]);
}

// ---- per-(b,h): kv fold, 64x64 attention, vals -----------------------------
__global__ __launch_bounds__(256) void attn_small(
    const float* __restrict__ Wkv, const float* __restrict__ bkv)
{
    const int bh = blockIdx.x;
    const int b = bh >> 3, h = bh & 7;
    __shared__ float segA[RR*65];
    __shared__ float segB[RR*65];
    __shared__ float segC[HDIM*65];
    const int tid = threadIdx.x;

    const int r1 = tid & 63, jg = tid >> 6;
    float acc[16];
#pragma unroll
    for (int jj = 0; jj < 16; jj++) acc[jj] = 0.f;
    const float* Sp = g_S + (size_t)bh*CC*RR;
    const float* Wp = Wkv + (size_t)(h*64)*CC;
    for (int c0 = 0; c0 < CC; c0 += 64) {
        for (int v = tid; v < 64*64; v += 256) {
            int cc = v >> 6, rr2 = v & 63;
            segA[cc*65 + rr2] = Sp[(size_t)(c0+cc)*RR + rr2];
        }
        for (int v = tid; v < 64*64; v += 256) {
            int j = v >> 6, cc = v & 63;
            segB[j*65 + cc] = Wp[(size_t)j*CC + c0 + cc];
        }
        __syncthreads();
        for (int cc = 0; cc < 64; cc++) {
            const float sv = segA[cc*65 + r1];
#pragma unroll
            for (int jj = 0; jj < 16; jj++)
                acc[jj] += segB[(jg*16+jj)*65 + cc] * sv;
        }
        __syncthreads();
    }
    {
        const float rs = g_rksum[b*RH + h*RR + r1];
#pragma unroll
        for (int jj = 0; jj < 16; jj++) {
            const int j = jg*16 + jj;
            segA[j*65 + r1] = acc[jj] + bkv[h*64 + j] * rs;
        }
    }
    for (int v = tid; v < HDIM*RR; v += 256) {
        int d = v >> 6, q = v & 63;
        segC[d*65 + q] = g_qr[(size_t)bh*HDIM*RR + v];
    }
    __syncthreads();

    {
        const float scale = rsqrtf((float)HDIM);
        const int k2 = tid & 63, qg = tid >> 6;
        for (int qq = 0; qq < 16; qq++) {
            const int q = qg*16 + qq;
            float s = 0.f;
#pragma unroll 8
            for (int d = 0; d < HDIM; d++)
                s += segC[d*65 + q] * segA[d*65 + k2];
            segB[q*65 + k2] = s * scale;
        }
    }
    __syncthreads();

    if (tid < 64) {
        float m = -1e30f;
        for (int k = 0; k < 64; k++) m = fmaxf(m, segB[tid*65 + k]);
        float s = 0.f;
        for (int k = 0; k < 64; k++) {
            const float e = __expf(segB[tid*65 + k] - m);
            segB[tid*65 + k] = e; s += e;
        }
        const float inv = 1.f / s;
        for (int k = 0; k < 64; k++) segB[tid*65 + k] *= inv;
    }
    __syncthreads();

    {
        const int q = tid & 63, dg = tid >> 6;
        float vacc[8];
#pragma unroll
        for (int dd = 0; dd < 8; dd++) vacc[dd] = 0.f;
        for (int k = 0; k < 64; k++) {
            const float av = segB[q*65 + k];
#pragma unroll
            for (int dd = 0; dd < 8; dd++)
                vacc[dd] += segA[(HDIM + dg*8 + dd)*65 + k] * av;
        }
#pragma unroll
        for (int dd = 0; dd < 8; dd++)
            g_vals[(size_t)bh*HDIM*RR + (dg*8+dd)*RR + q] = vacc[dd];
    }
}

// ---- tok[b][h*32+d][n] = sum_r vals[d][r]*Rq[h*64+r][n] --------------------
__global__ __launch_bounds__(256) void tok_kernel() {
    const int bh = blockIdx.y;
    const int b = bh >> 3, h = bh & 7;
    const int n0 = blockIdx.x * 256;
    __shared__ float Vt[RR][33];
    __shared__ float Bs[16][257];
    const int tid = threadIdx.x;
    for (int v = tid; v < HDIM*RR; v += 256) {
        int d = v >> 6, rr2 = v & 63;
        Vt[rr2][d] = g_vals[(size_t)bh*HDIM*RR + v];
    }
    const int lane = tid & 31, d0 = (tid >> 5) * 4;
    float acc[4][8];
#pragma unroll
    for (int i = 0; i < 4; i++)
#pragma unroll
        for (int j = 0; j < 8; j++) acc[i][j] = 0.f;
    const float* Rp = g_Rq + ((size_t)b*RH + h*RR)*NPIX + n0;
    for (int r0 = 0; r0 < RR; r0 += 16) {
        for (int v = tid; v < 16*256; v += 256) {
            int rr2 = v >> 8, nn = v & 255;
            Bs[rr2][nn] = Rp[(size_t)(r0+rr2)*NPIX + nn];
        }
        __syncthreads();
#pragma unroll 4
        for (int rr2 = 0; rr2 < 16; rr2++) {
            float a[4];
#pragma unroll
            for (int i = 0; i < 4; i++) a[i] = Vt[r0+rr2][d0+i];
#pragma unroll
            for (int j = 0; j < 8; j++) {
                const float bv = Bs[rr2][lane + j*32];
#pragma unroll
                for (int i = 0; i < 4; i++) acc[i][j] += a[i] * bv;
            }
        }
        __syncthreads();
    }
#pragma unroll
    for (int i = 0; i < 4; i++) {
        float* trow = g_tok + ((size_t)b*CC + h*HDIM + d0+i)*NPIX + n0;
#pragma unroll
        for (int j = 0; j < 8; j++) trow[lane + j*32] = acc[i][j];
    }
}

// ---- host launcher ----------------------------------------------------------
extern "C" void kernel_launch(void* const* d_in, const int* in_sizes, int n_in,
                              void* d_out, int out_size)
{
    const float* src    = (const float*)d_in[0];
    const float* tgt    = (const float*)d_in[1];
    const float* Wq     = (const float*)d_in[2];
    const float* bq     = (const float*)d_in[3];
    const float* Wkv    = (const float*)d_in[4];
    const float* bkv    = (const float*)d_in[5];
    const float* Wrq    = (const float*)d_in[6];
    const float* brq    = (const float*)d_in[7];
    const float* Wrk    = (const float*)d_in[8];
    const float* brk    = (const float*)d_in[9];
    const float* Wout   = (const float*)d_in[10];
    const float* bout   = (const float*)d_in[11];
    const float* alphap = (const float*)d_in[12];
    float* out = (float*)d_out;

    float *pq, *pRq, *pRk, *ptok, *pm, *ps;
    __nv_bfloat16 *pTt, *pSt, *pTOKt, *pWq, *pWrq, *pWrk, *pWout;
    cudaGetSymbolAddress((void**)&pq,    g_q);
    cudaGetSymbolAddress((void**)&pRq,   g_Rq);
    cudaGetSymbolAddress((void**)&pRk,   g_Rk);
    cudaGetSymbolAddress((void**)&ptok,  g_tok);
    cudaGetSymbolAddress((void**)&pm,    g_m);
    cudaGetSymbolAddress((void**)&ps,    g_s);
    cudaGetSymbolAddress((void**)&pTt,   g_Tt);
    cudaGetSymbolAddress((void**)&pSt,   g_St);
    cudaGetSymbolAddress((void**)&pTOKt, g_TOKt);
    cudaGetSymbolAddress((void**)&pWq,   g_WqHL);
    cudaGetSymbolAddress((void**)&pWrq,  g_WrqHL);
    cudaGetSymbolAddress((void**)&pWrk,  g_WrkHL);
    cudaGetSymbolAddress((void**)&pWout, g_WoutHL);

    const int SMEM = 131072;   // 2 stages x 64KB
    cudaFuncSetAttribute(hmma_gemm<false>,
        cudaFuncAttributeMaxDynamicSharedMemorySize, SMEM);
    cudaFuncSetAttribute(hmma_gemm<true>,
        cudaFuncAttributeMaxDynamicSharedMemorySize, SMEM);

    zero_acc<<<512, 256>>>();

    conv_w<<<(CC*CC + 255)/256, 256>>>(Wq,   pWq,   CC*CC);
    conv_w<<<(RH*CC + 255)/256, 256>>>(Wrq,  pWrq,  RH*CC);
    conv_w<<<(RH*CC + 255)/256, 256>>>(Wrk,  pWrk,  RH*CC);
    conv_w<<<(CC*CC + 255)/256, 256>>>(Wout, pWout, CC*CC);

    dim3 gt(NPIX/32, CC/32, BDIM);     // 288, 8, 8
    transpose_conv<<<gt, 256>>>(tgt, pTt);
    transpose_conv<<<gt, 256>>>(src, pSt);

    dim3 g2(NPIX/128, CC/128, BDIM);   // 72, 2, 8
    dim3 g4(NPIX/128, RH/128, BDIM);   // 72, 4, 8
    hmma_gemm<false><<<g2, 256, SMEM>>>(pWq,  bq,  pTt, pq,  CC, nullptr, nullptr);
    hmma_gemm<false><<<g4, 256, SMEM>>>(pWrq, brq, pTt, pRq, RH, nullptr, nullptr);
    hmma_gemm<false><<<g4, 256, SMEM>>>(pWrk, brk, pSt, pRk, RH, nullptr, nullptr);

    const int sgrid = (BDIM*NPIX + 255) / 256;   // 288
    softmax_ch_pass1<<<sgrid, 256>>>(pRq, pm, ps);
    softmax_ch_pass2<<<sgrid, 256>>>(pRq, pm, ps);
    softmax_ch_pass1<<<sgrid, 256>>>(pRk, pm, ps);
    softmax_ch_pass2<<<sgrid, 256>>>(pRk, pm, ps);

    rowsum_rk<<<BDIM*RH, 256>>>();

    contract_qr<<<dim3(BDIM*NHEADS, 18), 256>>>();
    contract_S <<<dim3(BDIM*NHEADS, 2, 4), 256>>>(src);

    attn_small<<<BDIM*NHEADS, 256>>>(Wkv, bkv);

    tok_kernel<<<dim3(NPIX/256, BDIM*NHEADS), 256>>>();

    transpose_conv<<<gt, 256>>>(ptok, pTOKt);
    hmma_gemm<true><<<g2, 256, SMEM>>>(pWout, bout, pTOKt, out, CC, tgt, alphap);
}

// round 12
// speedup vs baseline: 2.4258x; 1.2725x over previous
#include <cuda_runtime.h>
#include <cuda_bf16.h>
#include <math.h>
#include <stdint.h>

#define BDIM   8
#define CC     256
#define NPIX   9216          // 96*96
#define RH     512           // R*HEADS
#define NHEADS 8
#define HDIM   32
#define RR     64

// ---------------- scratch (device globals; no allocations allowed) ----------
__device__ float g_q   [BDIM*CC*NPIX];
__device__ float g_Rq  [BDIM*RH*NPIX];
__device__ float g_Rk  [BDIM*RH*NPIX];
__device__ float g_tok [BDIM*CC*NPIX];
__device__ float g_m   [BDIM*NPIX];
__device__ float g_s   [BDIM*NPIX];
__device__ float g_rksum[BDIM*RH];
__device__ float g_S   [BDIM*NHEADS*CC*RR];
__device__ float g_qr  [BDIM*NHEADS*HDIM*RR];
__device__ float g_vals[BDIM*NHEADS*HDIM*RR];

// bf16 hi/lo planes (16B aligned for uint4 loads)
__device__ __align__(16) __nv_bfloat16 g_Tt  [2ull*BDIM*NPIX*CC];  // tgt^T [2][b][n][k]
__device__ __align__(16) __nv_bfloat16 g_St  [2ull*BDIM*NPIX*CC];  // src^T
__device__ __align__(16) __nv_bfloat16 g_TOKt[2ull*BDIM*NPIX*CC];  // tok^T
__device__ __align__(16) __nv_bfloat16 g_Srcb[2ull*BDIM*CC*NPIX];  // src  [2][b][c][n]
__device__ __align__(16) __nv_bfloat16 g_Rkb [2ull*BDIM*RH*NPIX];  // Rk softmaxed [2][b][ch][n]
__device__ __align__(16) __nv_bfloat16 g_WqHL  [2*CC*CC];
__device__ __align__(16) __nv_bfloat16 g_WrqHL [2*RH*CC];
__device__ __align__(16) __nv_bfloat16 g_WrkHL [2*RH*CC];
__device__ __align__(16) __nv_bfloat16 g_WoutHL[2*CC*CC];

// ---------------- PTX helpers (baseline sm_80+ tensor path) ------------------
__device__ __forceinline__ uint32_t smem_u32(const void* p) {
    uint32_t a;
    asm("{ .reg .u64 t; cvta.to.shared.u64 t, %1; cvt.u32.u64 %0, t; }"
        : "=r"(a) : "l"(p));
    return a;
}
__device__ __forceinline__ void ldmx4(uint32_t* r, uint32_t addr) {
    asm volatile("ldmatrix.sync.aligned.m8n8.x4.shared.b16 {%0,%1,%2,%3}, [%4];"
        : "=r"(r[0]), "=r"(r[1]), "=r"(r[2]), "=r"(r[3]) : "r"(addr));
}
__device__ __forceinline__ void ldmx2(uint32_t* r, uint32_t addr) {
    asm volatile("ldmatrix.sync.aligned.m8n8.x2.shared.b16 {%0,%1}, [%2];"
        : "=r"(r[0]), "=r"(r[1]) : "r"(addr));
}
__device__ __forceinline__ void mma_bf16(float* c, const uint32_t* a, const uint32_t* b) {
    asm volatile("mma.sync.aligned.m16n8k16.row.col.f32.bf16.bf16.f32 "
        "{%0,%1,%2,%3}, {%4,%5,%6,%7}, {%8,%9}, {%0,%1,%2,%3};"
        : "+f"(c[0]), "+f"(c[1]), "+f"(c[2]), "+f"(c[3])
        : "r"(a[0]), "r"(a[1]), "r"(a[2]), "r"(a[3]), "r"(b[0]), "r"(b[1]));
}
__device__ __forceinline__ void cp16(uint32_t dst, const void* src) {
    asm volatile("cp.async.cg.shared.global [%0], [%1], 16;"
                 :: "r"(dst), "l"(src));
}
#define CP_COMMIT() asm volatile("cp.async.commit_group;" ::: "memory")
#define CP_WAIT(n)  asm volatile("cp.async.wait_group %0;" :: "n"(n) : "memory")

// ---------------- misc small kernels ----------------------------------------
__global__ void zero_acc() {
    const int t1 = BDIM*NHEADS*CC*RR;
    const int t2 = BDIM*NHEADS*HDIM*RR;
    for (int i = blockIdx.x*blockDim.x + threadIdx.x; i < t1 + t2;
         i += gridDim.x*blockDim.x) {
        if (i < t1) g_S[i] = 0.f;
        else        g_qr[i - t1] = 0.f;
    }
}

__global__ __launch_bounds__(256) void conv_w(
    const float* __restrict__ W, __nv_bfloat16* __restrict__ out, int total)
{
    int i = blockIdx.x*blockDim.x + threadIdx.x;
    if (i >= total) return;
    const float w = W[i];
    const __nv_bfloat16 hi = __float2bfloat16(w);
    out[i]         = hi;
    out[total + i] = __float2bfloat16(w - __bfloat162float(hi));
}

// X [B][256][9216] fp32 -> Xt [2][B][9216][256] bf16 (hi plane, lo plane)
__global__ __launch_bounds__(256) void transpose_conv(
    const float* __restrict__ X, __nv_bfloat16* __restrict__ Xt)
{
    __shared__ float tile[32][33];
    const int b = blockIdx.z, c0 = blockIdx.y*32, n0 = blockIdx.x*32;
    const int tx = threadIdx.x & 31, ty = threadIdx.x >> 5;   // 32x8
#pragma unroll
    for (int i = 0; i < 4; i++) {
        const int c = c0 + ty + 8*i;
        tile[ty + 8*i][tx] = X[((size_t)b*CC + c)*NPIX + n0 + tx];
    }
    __syncthreads();
    const size_t plane = (size_t)BDIM*NPIX*CC;
#pragma unroll
    for (int i = 0; i < 4; i++) {
        const int n = n0 + ty + 8*i;
        const float v = tile[tx][ty + 8*i];
        const __nv_bfloat16 hi = __float2bfloat16(v);
        const size_t o = ((size_t)b*NPIX + n)*CC + c0 + tx;
        Xt[o]         = hi;
        Xt[plane + o] = __float2bfloat16(v - __bfloat162float(hi));
    }
}

// ---------------- HMMA bf16x3 GEMM, 2-stage cp.async pipeline ----------------
// CTA tile M=128 x N=128(pixels), K chunked by 64. 8 warps 2(M)x4(N).
// Stage layout (64KB): A hi 16K | A lo 16K | B hi 16K | B lo 16K. 2 stages.
template<bool RESID>
__global__ __launch_bounds__(256, 1) void hmma_gemm(
    const __nv_bfloat16* __restrict__ Whl, const float* __restrict__ bias,
    const __nv_bfloat16* __restrict__ Xt, float* __restrict__ Y, int M,
    const float* __restrict__ resid, const float* __restrict__ alphap)
{
    extern __shared__ char sm[];
    const uint32_t sb = smem_u32(sm);
    const int tid = threadIdx.x, wid = tid >> 5, lane = tid & 31;
    const int n0 = blockIdx.x * 128, m0 = blockIdx.y * 128, b = blockIdx.z;
    const int mOff = (wid >> 2) * 64, nOff = (wid & 3) * 32;

    float acc[4][4][4];
#pragma unroll
    for (int mt = 0; mt < 4; mt++)
#pragma unroll
        for (int nt = 0; nt < 4; nt++)
#pragma unroll
            for (int i = 0; i < 4; i++) acc[mt][nt][i] = 0.f;

    const char* gA = (const char*)Whl + (size_t)m0 * 512;
    const size_t aPg = (size_t)M * 512;
    const char* gB = (const char*)Xt + ((size_t)b*NPIX + n0) * 512;
    const size_t bPg = (size_t)BDIM * NPIX * 512;

    const int lr = tid >> 3, lc = tid & 7;   // fill: 32 rows x 8 c16 per pass

#define ISSUE(k0, stg) do {                                                    \
    const uint32_t base_ = sb + (stg)*65536;                                   \
    _Pragma("unroll")                                                          \
    for (int p = 0; p < 2; p++) {                                              \
        const char* sA = gA + p*aPg + (k0)*2;                                  \
        const char* sB = gB + p*bPg + (k0)*2;                                  \
        _Pragma("unroll")                                                      \
        for (int it = 0; it < 4; it++) {                                       \
            const int row = lr + it*32;                                        \
            const uint32_t sw = row*128 + ((lc ^ (row & 7)) << 4);             \
            cp16(base_ + p*16384 + sw,         sA + (size_t)row*512 + lc*16);  \
            cp16(base_ + 32768 + p*16384 + sw, sB + (size_t)row*512 + lc*16);  \
        }                                                                      \
    }                                                                          \
    CP_COMMIT();                                                               \
} while (0)

    const int tr = lane & 15, tc = lane >> 4;
    const int br = lane & 7,  bc = (lane >> 3) & 1;

    ISSUE(0, 0);
#pragma unroll
    for (int c = 0; c < 4; c++) {
        if (c < 3) { ISSUE((c+1)*64, (c+1) & 1); CP_WAIT(1); }
        else       { CP_WAIT(0); }
        __syncthreads();
        const uint32_t base = sb + (c & 1)*65536;

#pragma unroll
        for (int kk = 0; kk < 4; kk++) {
            uint32_t ah[4][4], al_[4][4], bh[4][2], bl[4][2];
#pragma unroll
            for (int mt = 0; mt < 4; mt++) {
                const int row = mOff + mt*16 + tr;
                const int c16 = kk*2 + tc;
                const uint32_t ad = base + row*128 + ((c16 ^ (row & 7)) << 4);
                ldmx4(ah[mt],  ad);
                ldmx4(al_[mt], ad + 16384);
            }
#pragma unroll
            for (int nt = 0; nt < 4; nt++) {
                const int row = nOff + nt*8 + br;
                const int c16 = kk*2 + bc;
                const uint32_t bd = base + 32768 + row*128 + ((c16 ^ (row & 7)) << 4);
                ldmx2(bh[nt], bd);
                ldmx2(bl[nt], bd + 16384);
            }
#pragma unroll
            for (int mt = 0; mt < 4; mt++)
#pragma unroll
                for (int nt = 0; nt < 4; nt++) {
                    mma_bf16(acc[mt][nt], ah[mt],  bh[nt]);
                    mma_bf16(acc[mt][nt], ah[mt],  bl[nt]);
                    mma_bf16(acc[mt][nt], al_[mt], bh[nt]);
                }
        }
        __syncthreads();
    }
#undef ISSUE

    const float al = RESID ? *alphap : 0.f;
#pragma unroll
    for (int mt = 0; mt < 4; mt++) {
        const int r0 = m0 + mOff + mt*16 + (lane >> 2);
        const float bi0 = bias[r0], bi1 = bias[r0 + 8];
        float* y0 = Y + ((size_t)b*M + r0)*NPIX + n0;
        float* y1 = y0 + 8*NPIX;
        const float* rr0 = RESID ? (resid + ((size_t)b*M + r0)*NPIX + n0) : nullptr;
        const float* rr1 = RESID ? rr0 + 8*NPIX : nullptr;
#pragma unroll
        for (int nt = 0; nt < 4; nt++) {
            const int c = nOff + nt*8 + 2*(lane & 3);
            float2 v0, v1;
            v0.x = acc[mt][nt][0] + bi0; v0.y = acc[mt][nt][1] + bi0;
            v1.x = acc[mt][nt][2] + bi1; v1.y = acc[mt][nt][3] + bi1;
            if (RESID) {
                const float2 a0 = *(const float2*)&rr0[c];
                const float2 a1 = *(const float2*)&rr1[c];
                v0.x = a0.x + al*v0.x; v0.y = a0.y + al*v0.y;
                v1.x = a1.x + al*v1.x; v1.y = a1.y + al*v1.y;
            }
            *(float2*)&y0[c] = v0;
            *(float2*)&y1[c] = v1;
        }
    }
}

// ---------------- HMMA S: S[bh][c][r] += src_b @ Rk_b^T ----------------------
// M=256(c) x N=512(h*64+r) x K=9216(n), K-split 2. Same pipeline as hmma_gemm
// but both operands row-stride NPIX*2 bytes. Epilogue: atomicAdd into g_S
// with the existing [bh][CC][RR] layout (attn_small unchanged).
__global__ __launch_bounds__(256, 1) void hmma_S()
{
    extern __shared__ char sm[];
    const uint32_t sb = smem_u32(sm);
    const int tid = threadIdx.x, wid = tid >> 5, lane = tid & 31;
    const int n0 = blockIdx.x * 128, m0 = blockIdx.y * 128;
    const int b = blockIdx.z >> 1, ks = blockIdx.z & 1;
    const int mOff = (wid >> 2) * 64, nOff = (wid & 3) * 32;

    float acc[4][4][4];
#pragma unroll
    for (int mt = 0; mt < 4; mt++)
#pragma unroll
        for (int nt = 0; nt < 4; nt++)
#pragma unroll
            for (int i = 0; i < 4; i++) acc[mt][nt][i] = 0.f;

    const char* gA = (const char*)g_Srcb + (((size_t)b*CC + m0)*NPIX + ks*4608) * 2;
    const size_t aPg = (size_t)BDIM * CC * NPIX * 2;
    const char* gB = (const char*)g_Rkb  + (((size_t)b*RH + n0)*NPIX + ks*4608) * 2;
    const size_t bPg = (size_t)BDIM * RH * NPIX * 2;

    const int lr = tid >> 3, lc = tid & 7;

#define ISSUE_S(k0, stg) do {                                                  \
    const uint32_t base_ = sb + (stg)*65536;                                   \
    _Pragma("unroll")                                                          \
    for (int p = 0; p < 2; p++) {                                              \
        const char* sA = gA + p*aPg + (k0)*2;                                  \
        const char* sB = gB + p*bPg + (k0)*2;                                  \
        _Pragma("unroll")                                                      \
        for (int it = 0; it < 4; it++) {                                       \
            const int row = lr + it*32;                                        \
            const uint32_t sw = row*128 + ((lc ^ (row & 7)) << 4);             \
            cp16(base_ + p*16384 + sw,         sA + (size_t)row*(NPIX*2) + lc*16); \
            cp16(base_ + 32768 + p*16384 + sw, sB + (size_t)row*(NPIX*2) + lc*16); \
        }                                                                      \
    }                                                                          \
    CP_COMMIT();                                                               \
} while (0)

    const int tr = lane & 15, tc = lane >> 4;
    const int br = lane & 7,  bc = (lane >> 3) & 1;

    ISSUE_S(0, 0);
    for (int c = 0; c < 72; c++) {       // 72 x 64 = 4608 K per split
        if (c < 71) { ISSUE_S((c+1)*64, (c+1) & 1); CP_WAIT(1); }
        else        { CP_WAIT(0); }
        __syncthreads();
        const uint32_t base = sb + (c & 1)*65536;

#pragma unroll
        for (int kk = 0; kk < 4; kk++) {
            uint32_t ah[4][4], al_[4][4], bh[4][2], bl[4][2];
#pragma unroll
            for (int mt = 0; mt < 4; mt++) {
                const int row = mOff + mt*16 + tr;
                const int c16 = kk*2 + tc;
                const uint32_t ad = base + row*128 + ((c16 ^ (row & 7)) << 4);
                ldmx4(ah[mt],  ad);
                ldmx4(al_[mt], ad + 16384);
            }
#pragma unroll
            for (int nt = 0; nt < 4; nt++) {
                const int row = nOff + nt*8 + br;
                const int c16 = kk*2 + bc;
                const uint32_t bd = base + 32768 + row*128 + ((c16 ^ (row & 7)) << 4);
                ldmx2(bh[nt], bd);
                ldmx2(bl[nt], bd + 16384);
            }
#pragma unroll
            for (int mt = 0; mt < 4; mt++)
#pragma unroll
                for (int nt = 0; nt < 4; nt++) {
                    mma_bf16(acc[mt][nt], ah[mt],  bh[nt]);
                    mma_bf16(acc[mt][nt], ah[mt],  bl[nt]);
                    mma_bf16(acc[mt][nt], al_[mt], bh[nt]);
                }
        }
        __syncthreads();
    }
#undef ISSUE_S

#pragma unroll
    for (int mt = 0; mt < 4; mt++) {
        const int c0r = m0 + mOff + mt*16 + (lane >> 2);   // channel c
#pragma unroll
        for (int nt = 0; nt < 4; nt++) {
            const int n = n0 + nOff + nt*8 + 2*(lane & 3); // h*64+r (even)
            const int h = n >> 6, r = n & 63;
            float* d0 = g_S + (((size_t)(b*NHEADS + h)*CC + c0r)*RR) + r;
            atomicAdd(&d0[0],      acc[mt][nt][0]);
            atomicAdd(&d0[1],      acc[mt][nt][1]);
            atomicAdd(&d0[8*RR],   acc[mt][nt][2]);   // channel c+8
            atomicAdd(&d0[8*RR+1], acc[mt][nt][3]);
        }
    }
}

// ---- channel softmax over 512 channels, per pixel column -------------------
__global__ __launch_bounds__(256) void softmax_ch_pass1(
    const float* __restrict__ X, float* __restrict__ gm, float* __restrict__ gs)
{
    const int idx = blockIdx.x * blockDim.x + threadIdx.x;
    if (idx >= BDIM*NPIX) return;
    const int b = idx / NPIX, n = idx - b*NPIX;
    const float* col = X + (size_t)b*RH*NPIX + n;
    float m = -1e30f, s = 0.f;
    for (int c = 0; c < RH; c++) {
        const float x = col[(size_t)c*NPIX];
        const float m2 = fmaxf(m, x);
        s = s * __expf(m - m2) + __expf(x - m2);
        m = m2;
    }
    gm[idx] = m; gs[idx] = s;
}

// fp32 writeback variant (Rq: tok_kernel + contract_qr read fp32)
__global__ __launch_bounds__(256) void softmax_ch_pass2(
    float* __restrict__ X, const float* __restrict__ gm, const float* __restrict__ gs)
{
    const int idx = blockIdx.x * blockDim.x + threadIdx.x;
    if (idx >= BDIM*NPIX) return;
    const int b = idx / NPIX, n = idx - b*NPIX;
    float* col = X + (size_t)b*RH*NPIX + n;
    const float m = gm[idx], inv = 1.f / gs[idx];
    for (int c = 0; c < RH; c++) {
        float* p = col + (size_t)c*NPIX;
        *p = __expf(*p - m) * inv;
    }
}

// bf16 hi/lo plane variant (Rk: consumed only by hmma_S + rowsum)
__global__ __launch_bounds__(256) void softmax_ch_pass2_bf16(
    const float* __restrict__ X, const float* __restrict__ gm,
    const float* __restrict__ gs, __nv_bfloat16* __restrict__ Xb)
{
    const int idx = blockIdx.x * blockDim.x + threadIdx.x;
    if (idx >= BDIM*NPIX) return;
    const int b = idx / NPIX, n = idx - b*NPIX;
    const float* col = X + (size_t)b*RH*NPIX + n;
    __nv_bfloat16* colb = Xb + (size_t)b*RH*NPIX + n;
    const size_t PS = (size_t)BDIM*RH*NPIX;
    const float m = gm[idx], inv = 1.f / gs[idx];
    for (int c = 0; c < RH; c++) {
        const float v = __expf(col[(size_t)c*NPIX] - m) * inv;
        const __nv_bfloat16 hi = __float2bfloat16(v);
        colb[(size_t)c*NPIX]      = hi;
        colb[PS + (size_t)c*NPIX] = __float2bfloat16(v - __bfloat162float(hi));
    }
}

// ---- row sums of softmaxed Rk (bf16 hi+lo planes) --------------------------
__global__ __launch_bounds__(256) void rowsum_rk(const __nv_bfloat16* __restrict__ Rkb) {
    const int row = blockIdx.x;                 // B*RH rows
    const size_t PS = (size_t)BDIM*RH*NPIX;
    const __nv_bfloat16* ph = Rkb + (size_t)row * NPIX;
    float s = 0.f;
    for (int n = threadIdx.x; n < NPIX; n += 256)
        s += __bfloat162float(ph[n]) + __bfloat162float(ph[PS + n]);
    __shared__ float red[256];
    red[threadIdx.x] = s; __syncthreads();
    for (int o = 128; o > 0; o >>= 1) {
        if (threadIdx.x < o) red[threadIdx.x] += red[threadIdx.x + o];
        __syncthreads();
    }
    if (threadIdx.x == 0) g_rksum[row] = red[0];
}

// ---- qr[b,h][32x64] = q_h @ Rq_h^T  (K-split over NPIX, atomic) ------------
__global__ __launch_bounds__(256) void contract_qr() {
    const int bh = blockIdx.x;
    const int b = bh >> 3, h = bh & 7;
    const int kbase = blockIdx.y * 512;
    const float* Q  = g_q  + ((size_t)b*CC + h*HDIM)*NPIX;
    const float* Rr = g_Rq + ((size_t)b*RH + h*RR)*NPIX;
    __shared__ float Qs[HDIM][33];
    __shared__ float Rs[RR][33];
    const int tid = threadIdx.x;
    const int r = tid & 63, d0 = (tid >> 6) * 8;
    float acc[8] = {};
    for (int t = 0; t < 16; t++) {
        const int kg = kbase + t*32;
        for (int v = tid; v < HDIM*32; v += 256) {
            int i = v >> 5, kk = v & 31;
            Qs[i][kk] = Q[(size_t)i*NPIX + kg + kk];
        }
        for (int v = tid; v < RR*32; v += 256) {
            int i = v >> 5, kk = v & 31;
            Rs[i][kk] = Rr[(size_t)i*NPIX + kg + kk];
        }
        __syncthreads();
#pragma unroll 4
        for (int kk = 0; kk < 32; kk++) {
            const float rv = Rs[r][kk];
#pragma unroll
            for (int i = 0; i < 8; i++) acc[i] += Qs[d0+i][kk] * rv;
        }
        __syncthreads();
    }
#pragma unroll
    for (int i = 0; i < 8; i++)
        atomicAdd(&g_qr[(size_t)bh*HDIM*RR + (d0+i)*RR + r], acc[i]);
}

// ---- per-(b,h): kv fold, 64x64 attention, vals -----------------------------
__global__ __launch_bounds__(256) void attn_small(
    const float* __restrict__ Wkv, const float* __restrict__ bkv)
{
    const int bh = blockIdx.x;
    const int b = bh >> 3, h = bh & 7;
    __shared__ float segA[RR*65];
    __shared__ float segB[RR*65];
    __shared__ float segC[HDIM*65];
    const int tid = threadIdx.x;

    const int r1 = tid & 63, jg = tid >> 6;
    float acc[16];
#pragma unroll
    for (int jj = 0; jj < 16; jj++) acc[jj] = 0.f;
    const float* Sp = g_S + (size_t)bh*CC*RR;
    const float* Wp = Wkv + (size_t)(h*64)*CC;
    for (int c0 = 0; c0 < CC; c0 += 64) {
        for (int v = tid; v < 64*64; v += 256) {
            int cc = v >> 6, rr2 = v & 63;
            segA[cc*65 + rr2] = Sp[(size_t)(c0+cc)*RR + rr2];
        }
        for (int v = tid; v < 64*64; v += 256) {
            int j = v >> 6, cc = v & 63;
            segB[j*65 + cc] = Wp[(size_t)j*CC + c0 + cc];
        }
        __syncthreads();
        for (int cc = 0; cc < 64; cc++) {
            const float sv = segA[cc*65 + r1];
#pragma unroll
            for (int jj = 0; jj < 16; jj++)
                acc[jj] += segB[(jg*16+jj)*65 + cc] * sv;
        }
        __syncthreads();
    }
    {
        const float rs = g_rksum[b*RH + h*RR + r1];
#pragma unroll
        for (int jj = 0; jj < 16; jj++) {
            const int j = jg*16 + jj;
            segA[j*65 + r1] = acc[jj] + bkv[h*64 + j] * rs;
        }
    }
    for (int v = tid; v < HDIM*RR; v += 256) {
        int d = v >> 6, q = v & 63;
        segC[d*65 + q] = g_qr[(size_t)bh*HDIM*RR + v];
    }
    __syncthreads();

    {
        const float scale = rsqrtf((float)HDIM);
        const int k2 = tid & 63, qg = tid >> 6;
        for (int qq = 0; qq < 16; qq++) {
            const int q = qg*16 + qq;
            float s = 0.f;
#pragma unroll 8
            for (int d = 0; d < HDIM; d++)
                s += segC[d*65 + q] * segA[d*65 + k2];
            segB[q*65 + k2] = s * scale;
        }
    }
    __syncthreads();

    if (tid < 64) {
        float m = -1e30f;
        for (int k = 0; k < 64; k++) m = fmaxf(m, segB[tid*65 + k]);
        float s = 0.f;
        for (int k = 0; k < 64; k++) {
            const float e = __expf(segB[tid*65 + k] - m);
            segB[tid*65 + k] = e; s += e;
        }
        const float inv = 1.f / s;
        for (int k = 0; k < 64; k++) segB[tid*65 + k] *= inv;
    }
    __syncthreads();

    {
        const int q = tid & 63, dg = tid >> 6;
        float vacc[8];
#pragma unroll
        for (int dd = 0; dd < 8; dd++) vacc[dd] = 0.f;
        for (int k = 0; k < 64; k++) {
            const float av = segB[q*65 + k];
#pragma unroll
            for (int dd = 0; dd < 8; dd++)
                vacc[dd] += segA[(HDIM + dg*8 + dd)*65 + k] * av;
        }
#pragma unroll
        for (int dd = 0; dd < 8; dd++)
            g_vals[(size_t)bh*HDIM*RR + (dg*8+dd)*RR + q] = vacc[dd];
    }
}

// ---- tok[b][h*32+d][n] = sum_r vals[d][r]*Rq[h*64+r][n] --------------------
__global__ __launch_bounds__(256) void tok_kernel() {
    const int bh = blockIdx.y;
    const int b = bh >> 3, h = bh & 7;
    const int n0 = blockIdx.x * 256;
    __shared__ float Vt[RR][33];
    __shared__ float Bs[16][257];
    const int tid = threadIdx.x;
    for (int v = tid; v < HDIM*RR; v += 256) {
        int d = v >> 6, rr2 = v & 63;
        Vt[rr2][d] = g_vals[(size_t)bh*HDIM*RR + v];
    }
    const int lane = tid & 31, d0 = (tid >> 5) * 4;
    float acc[4][8];
#pragma unroll
    for (int i = 0; i < 4; i++)
#pragma unroll
        for (int j = 0; j < 8; j++) acc[i][j] = 0.f;
    const float* Rp = g_Rq + ((size_t)b*RH + h*RR)*NPIX + n0;
    for (int r0 = 0; r0 < RR; r0 += 16) {
        for (int v = tid; v < 16*256; v += 256) {
            int rr2 = v >> 8, nn = v & 255;
            Bs[rr2][nn] = Rp[(size_t)(r0+rr2)*NPIX + nn];
        }
        __syncthreads();
#pragma unroll 4
        for (int rr2 = 0; rr2 < 16; rr2++) {
            float a[4];
#pragma unroll
            for (int i = 0; i < 4; i++) a[i] = Vt[r0+rr2][d0+i];
#pragma unroll
            for (int j = 0; j < 8; j++) {
                const float bv = Bs[rr2][lane + j*32];
#pragma unroll
                for (int i = 0; i < 4; i++) acc[i][j] += a[i] * bv;
            }
        }
        __syncthreads();
    }
#pragma unroll
    for (int i = 0; i < 4; i++) {
        float* trow = g_tok + ((size_t)b*CC + h*HDIM + d0+i)*NPIX + n0;
#pragma unroll
        for (int j = 0; j < 8; j++) trow[lane + j*32] = acc[i][j];
    }
}

// ---- host launcher ----------------------------------------------------------
extern "C" void kernel_launch(void* const* d_in, const int* in_sizes, int n_in,
                              void* d_out, int out_size)
{
    const float* src    = (const float*)d_in[0];
    const float* tgt    = (const float*)d_in[1];
    const float* Wq     = (const float*)d_in[2];
    const float* bq     = (const float*)d_in[3];
    const float* Wkv    = (const float*)d_in[4];
    const float* bkv    = (const float*)d_in[5];
    const float* Wrq    = (const float*)d_in[6];
    const float* brq    = (const float*)d_in[7];
    const float* Wrk    = (const float*)d_in[8];
    const float* brk    = (const float*)d_in[9];
    const float* Wout   = (const float*)d_in[10];
    const float* bout   = (const float*)d_in[11];
    const float* alphap = (const float*)d_in[12];
    float* out = (float*)d_out;

    float *pq, *pRq, *pRk, *ptok, *pm, *ps;
    __nv_bfloat16 *pTt, *pSt, *pTOKt, *pSrcb, *pRkb, *pWq, *pWrq, *pWrk, *pWout;
    cudaGetSymbolAddress((void**)&pq,    g_q);
    cudaGetSymbolAddress((void**)&pRq,   g_Rq);
    cudaGetSymbolAddress((void**)&pRk,   g_Rk);
    cudaGetSymbolAddress((void**)&ptok,  g_tok);
    cudaGetSymbolAddress((void**)&pm,    g_m);
    cudaGetSymbolAddress((void**)&ps,    g_s);
    cudaGetSymbolAddress((void**)&pTt,   g_Tt);
    cudaGetSymbolAddress((void**)&pSt,   g_St);
    cudaGetSymbolAddress((void**)&pTOKt, g_TOKt);
    cudaGetSymbolAddress((void**)&pSrcb, g_Srcb);
    cudaGetSymbolAddress((void**)&pRkb,  g_Rkb);
    cudaGetSymbolAddress((void**)&pWq,   g_WqHL);
    cudaGetSymbolAddress((void**)&pWrq,  g_WrqHL);
    cudaGetSymbolAddress((void**)&pWrk,  g_WrkHL);
    cudaGetSymbolAddress((void**)&pWout, g_WoutHL);

    const int SMEM = 131072;   // 2 stages x 64KB
    cudaFuncSetAttribute(hmma_gemm<false>,
        cudaFuncAttributeMaxDynamicSharedMemorySize, SMEM);
    cudaFuncSetAttribute(hmma_gemm<true>,
        cudaFuncAttributeMaxDynamicSharedMemorySize, SMEM);
    cudaFuncSetAttribute(hmma_S,
        cudaFuncAttributeMaxDynamicSharedMemorySize, SMEM);

    zero_acc<<<512, 256>>>();

    conv_w<<<(CC*CC + 255)/256, 256>>>(Wq,   pWq,   CC*CC);
    conv_w<<<(RH*CC + 255)/256, 256>>>(Wrq,  pWrq,  RH*CC);
    conv_w<<<(RH*CC + 255)/256, 256>>>(Wrk,  pWrk,  RH*CC);
    conv_w<<<(CC*CC + 255)/256, 256>>>(Wout, pWout, CC*CC);
    conv_w<<<(BDIM*CC*NPIX + 255)/256, 256>>>(src, pSrcb, BDIM*CC*NPIX);

    dim3 gt(NPIX/32, CC/32, BDIM);     // 288, 8, 8
    transpose_conv<<<gt, 256>>>(tgt, pTt);
    transpose_conv<<<gt, 256>>>(src, pSt);

    dim3 g2(NPIX/128, CC/128, BDIM);   // 72, 2, 8
    dim3 g4(NPIX/128, RH/128, BDIM);   // 72, 4, 8
    hmma_gemm<false><<<g2, 256, SMEM>>>(pWq,  bq,  pTt, pq,  CC, nullptr, nullptr);
    hmma_gemm<false><<<g4, 256, SMEM>>>(pWrq, brq, pTt, pRq, RH, nullptr, nullptr);
    hmma_gemm<false><<<g4, 256, SMEM>>>(pWrk, brk, pSt, pRk, RH, nullptr, nullptr);

    const int sgrid = (BDIM*NPIX + 255) / 256;   // 288
    softmax_ch_pass1<<<sgrid, 256>>>(pRq, pm, ps);
    softmax_ch_pass2<<<sgrid, 256>>>(pRq, pm, ps);
    softmax_ch_pass1<<<sgrid, 256>>>(pRk, pm, ps);
    softmax_ch_pass2_bf16<<<sgrid, 256>>>(pRk, pm, ps, pRkb);

    rowsum_rk<<<BDIM*RH, 256>>>(pRkb);

    contract_qr<<<dim3(BDIM*NHEADS, 18), 256>>>();
    hmma_S<<<dim3(RH/128, CC/128, BDIM*2), 256, SMEM>>>();   // 4,2,16

    attn_small<<<BDIM*NHEADS, 256>>>(Wkv, bkv);

    tok_kernel<<<dim3(NPIX/256, BDIM*NHEADS), 256>>>();

    transpose_conv<<<gt, 256>>>(ptok, pTOKt);
    hmma_gemm<true><<<g2, 256, SMEM>>>(pWout, bout, pTOKt, out, CC, tgt, alphap);
}